// round 2
// baseline (speedup 1.0000x reference)
#include <cuda_runtime.h>
#include <cuda_bf16.h>
#include <mma.h>
#include <cstdint>

using namespace nvcuda;

// Problem shape (fixed for this dataset)
#define NNODES 50000
#define MPAD   50048          // padded to multiple of 128
#define FDIM   128            // node feature dim (also output dim)
#define KNB    32             // neighbors per node
#define EDIM   16             // edge feature dim
#define KK     2048           // FDIM * EDIM  (GEMM K)

// Scratch (device globals are zero-initialized at module load; pad rows stay 0)
__device__ float g_buf[(size_t)MPAD * KK];      // [i][l*16+n]  ~410 MB
__device__ float W2[KK * FDIM];                 // [k=(l*16+n)][m]  1 MB
__device__ float Cpad[(size_t)MPAD * FDIM];     // padded GEMM output ~25.6 MB
__device__ int   g_nlist_is64;                  // runtime dtype flag

// ---------------------------------------------------------------------------
// Kernel -1: detect whether nlist is int64 (odd 32-bit words all zero) or int32
// ---------------------------------------------------------------------------
__global__ void detect_nlist(const int* __restrict__ nl) {
    int odd_or = 0;
#pragma unroll
    for (int t = 1; t < 64; t += 2) odd_or |= nl[t];
    g_nlist_is64 = (odd_or == 0) ? 1 : 0;
}

// ---------------------------------------------------------------------------
// Kernel 0: W2[(l*16+n)*128 + m] = tf32(w[l,m,n])
// ---------------------------------------------------------------------------
__global__ void build_w2(const float* __restrict__ w) {
    int idx = blockIdx.x * 256 + threadIdx.x;
    if (idx < KK * FDIM) {
        int m = idx & (FDIM - 1);
        int k = idx >> 7;
        int l = k >> 4;
        int n = k & (EDIM - 1);
        W2[idx] = wmma::__float_to_tf32(w[(size_t)l * FDIM * EDIM + (size_t)m * EDIM + n]);
    }
}

// ---------------------------------------------------------------------------
// Kernel 1: g[i,l,n] = sum_j nodes[nlist[i,j], l] * edges[i,j,n]
// One CTA per node, 128 threads (thread = l). nodes (25.6MB) is L2-resident,
// so the 32 gathered 512B rows per CTA hit L2.
// ---------------------------------------------------------------------------
__global__ void gather_contract(const float* __restrict__ nodes,
                                const int* __restrict__ nlist32,
                                const float* __restrict__ edges) {
    int i = blockIdx.x;
    int l = threadIdx.x;  // 0..127

    __shared__ __align__(16) float se[KNB * EDIM];  // 512 floats
    __shared__ int snb[KNB];

    // edges[i] : 512 floats -> 128 float4, one per thread (coalesced)
    ((float4*)se)[l] = ((const float4*)(edges + (size_t)i * KNB * EDIM))[l];
    if (l < KNB) {
        int pos = i * KNB + l;
        int idx = g_nlist_is64 ? nlist32[2 * (size_t)pos]   // low word of int64
                               : nlist32[pos];
        // clamp: any surprise becomes a rel_err signal, not a crash
        idx = idx < 0 ? 0 : (idx >= NNODES ? NNODES - 1 : idx);
        snb[l] = idx;
    }
    __syncthreads();

    float acc[EDIM];
#pragma unroll
    for (int n = 0; n < EDIM; n++) acc[n] = 0.f;

#pragma unroll 4
    for (int j = 0; j < KNB; j++) {
        float v = __ldg(nodes + (size_t)snb[j] * FDIM + l);  // coalesced 512B row
#pragma unroll
        for (int n = 0; n < EDIM; n++)
            acc[n] = fmaf(v, se[j * EDIM + n], acc[n]);
    }

    // pre-round to tf32 so the GEMM needs no conversion
    float4* g4 = (float4*)(g_buf + (size_t)i * KK + (size_t)l * EDIM);
#pragma unroll
    for (int q = 0; q < 4; q++) {
        g4[q] = make_float4(wmma::__float_to_tf32(acc[q * 4 + 0]),
                            wmma::__float_to_tf32(acc[q * 4 + 1]),
                            wmma::__float_to_tf32(acc[q * 4 + 2]),
                            wmma::__float_to_tf32(acc[q * 4 + 3]));
    }
}

// ---------------------------------------------------------------------------
// Kernel 2: Cpad = (1/32) * g_buf @ W2   (M=50048, N=128, K=2048), tf32 wmma
// BM=128, BN=128, BK=16; 256 threads = 8 warps; warp tile 32x64 (2x4 wmma)
// cp.async double-buffered smem pipeline.
// ---------------------------------------------------------------------------
#define BM 128
#define BN 128
#define BK 16

__device__ __forceinline__ void cp16(void* s, const void* g) {
    uint32_t sa = (uint32_t)__cvta_generic_to_shared(s);
    asm volatile("cp.async.cg.shared.global [%0], [%1], 16;\n" :: "r"(sa), "l"(g));
}
__device__ __forceinline__ void cp_commit() { asm volatile("cp.async.commit_group;\n"); }
__device__ __forceinline__ void cp_wait0()  { asm volatile("cp.async.wait_group 0;\n"); }

__global__ __launch_bounds__(256) void gemm_tf32() {
    __shared__ __align__(16) float As[2][BM][BK];   // 2 x 8 KB
    __shared__ __align__(16) float Bs[2][BK][BN];   // 2 x 8 KB

    int tid = threadIdx.x;
    int wid = tid >> 5;
    int warp_m = wid >> 1;   // 0..3 -> 32 rows each
    int warp_n = wid & 1;    // 0..1 -> 64 cols each
    size_t row0 = (size_t)blockIdx.x * BM;

    wmma::fragment<wmma::accumulator, 16, 16, 8, float> c[2][4];
#pragma unroll
    for (int mi = 0; mi < 2; mi++)
#pragma unroll
        for (int ni = 0; ni < 4; ni++)
            wmma::fill_fragment(c[mi][ni], 0.0f);

    auto load_tiles = [&](int buf, int kb) {
        const float* Ab = g_buf + row0 * KK + (size_t)kb * BK;
        const float* Bb = W2 + (size_t)kb * BK * BN;
        int q0 = tid * 2;
#pragma unroll
        for (int u = 0; u < 2; u++) {
            int q = q0 + u;
            int ar = q >> 2, ac = (q & 3) * 4;      // A: 128 rows x 16 cols
            cp16(&As[buf][ar][ac], Ab + (size_t)ar * KK + ac);
            int br = q >> 5, bc = (q & 31) * 4;     // B: 16 rows x 128 cols
            cp16(&Bs[buf][br][bc], Bb + br * BN + bc);
        }
        cp_commit();
    };

    load_tiles(0, 0);
    cp_wait0();
    __syncthreads();

    const int nkb = KK / BK;  // 128
    for (int kb = 0; kb < nkb; kb++) {
        int cur = kb & 1;
        if (kb + 1 < nkb) load_tiles(cur ^ 1, kb + 1);

#pragma unroll
        for (int kk = 0; kk < 2; kk++) {
            wmma::fragment<wmma::matrix_a, 16, 16, 8, wmma::precision::tf32, wmma::row_major> a[2];
            wmma::fragment<wmma::matrix_b, 16, 16, 8, wmma::precision::tf32, wmma::row_major> b[4];
#pragma unroll
            for (int mi = 0; mi < 2; mi++)
                wmma::load_matrix_sync(a[mi], &As[cur][warp_m * 32 + mi * 16][kk * 8], BK);
#pragma unroll
            for (int ni = 0; ni < 4; ni++)
                wmma::load_matrix_sync(b[ni], &Bs[cur][kk * 8][warp_n * 64 + ni * 16], BN);
#pragma unroll
            for (int mi = 0; mi < 2; mi++)
#pragma unroll
                for (int ni = 0; ni < 4; ni++)
                    wmma::mma_sync(c[mi][ni], a[mi], b[ni], c[mi][ni]);
        }

        if (kb + 1 < nkb) cp_wait0();
        __syncthreads();
    }

    const float scale = 1.0f / (float)KNB;
#pragma unroll
    for (int mi = 0; mi < 2; mi++)
#pragma unroll
        for (int ni = 0; ni < 4; ni++) {
#pragma unroll
            for (int t = 0; t < c[mi][ni].num_elements; t++) c[mi][ni].x[t] *= scale;
            float* dst = Cpad + (row0 + warp_m * 32 + mi * 16) * FDIM + warp_n * 64 + ni * 16;
            wmma::store_matrix_sync(dst, c[mi][ni], FDIM, wmma::mem_row_major);
        }
}

// ---------------------------------------------------------------------------
// Kernel 3: copy valid rows of Cpad -> d_out (float4)
// ---------------------------------------------------------------------------
__global__ void copy_out(float* __restrict__ out) {
    size_t i = (size_t)blockIdx.x * 256 + threadIdx.x;
    if (i < (size_t)NNODES * FDIM / 4)
        ((float4*)out)[i] = ((const float4*)Cpad)[i];
}

// ---------------------------------------------------------------------------
extern "C" void kernel_launch(void* const* d_in, const int* in_sizes, int n_in,
                              void* d_out, int out_size) {
    // Identify inputs by element count (all four are distinct) — immune to
    // metadata ordering surprises. Fall back to positional if needed.
    const float* nodes = nullptr;
    const int*   nlist = nullptr;   // read as 32-bit words; dtype detected on device
    const float* edges = nullptr;
    const float* w     = nullptr;
    for (int t = 0; t < n_in; t++) {
        long long s = in_sizes[t];
        if      (s == (long long)NNODES * FDIM)        nodes = (const float*)d_in[t];
        else if (s == (long long)NNODES * KNB)         nlist = (const int*)d_in[t];
        else if (s == (long long)NNODES * KNB * EDIM)  edges = (const float*)d_in[t];
        else if (s == (long long)FDIM * FDIM * EDIM)   w     = (const float*)d_in[t];
    }
    if (!nodes) nodes = (const float*)d_in[0];
    if (!nlist) nlist = (const int*)d_in[1];
    if (!edges) edges = (const float*)d_in[2];
    if (!w)     w     = (const float*)d_in[3];

    float* out = (float*)d_out;

    detect_nlist<<<1, 1>>>(nlist);
    build_w2<<<(KK * FDIM + 255) / 256, 256>>>(w);
    gather_contract<<<NNODES, FDIM>>>(nodes, nlist, edges);
    gemm_tf32<<<MPAD / BM, 256>>>();
    copy_out<<<(NNODES * FDIM / 4 + 255) / 256, 256>>>(out);
}

// round 6
// speedup vs baseline: 1.0130x; 1.0130x over previous
#include <cuda_runtime.h>
#include <mma.h>
#include <cstdint>

using namespace nvcuda;

#define NNODES 50000
#define MPAD   50048
#define FDIM   128
#define KNB    32
#define EDIM   16
#define KK     2048          // FDIM * EDIM
#define GRID1  592           // stage-1 CTAs

__device__ float g_buf[(size_t)MPAD * KK];   // [i][l*16+n], pad rows stay 0
__device__ float W2[KK * FDIM];              // [k=(l*16+n)][m]
__device__ float Ctail[128 * FDIM];          // last-block GEMM scratch
__device__ int   g_nlist_is64;

// ---------------------------------------------------------------------------
__global__ void detect_nlist(const int* __restrict__ nl) {
    int odd_or = 0;
#pragma unroll
    for (int t = 1; t < 64; t += 2) odd_or |= nl[t];
    g_nlist_is64 = (odd_or == 0) ? 1 : 0;
}

// W2[(l*16+n)*128 + m] = tf32(w[l,m,n])
__global__ void build_w2(const float* __restrict__ w) {
    int idx = blockIdx.x * 256 + threadIdx.x;
    if (idx < KK * FDIM) {
        int m = idx & (FDIM - 1);
        int k = idx >> 7;
        int l = k >> 4;
        int n = k & (EDIM - 1);
        W2[idx] = wmma::__float_to_tf32(w[(size_t)l * FDIM * EDIM + (size_t)m * EDIM + n]);
    }
}

// ---------------------------------------------------------------------------
__device__ __forceinline__ void cp16(void* s, const void* g) {
    uint32_t sa = (uint32_t)__cvta_generic_to_shared(s);
    asm volatile("cp.async.cg.shared.global [%0], [%1], 16;\n" :: "r"(sa), "l"(g));
}
__device__ __forceinline__ void cp_commit() { asm volatile("cp.async.commit_group;\n"); }
template <int N>
__device__ __forceinline__ void cp_wait() { asm volatile("cp.async.wait_group %0;\n" :: "n"(N)); }

// ---------------------------------------------------------------------------
// Stage 1 (3x tf32 split MMA, fp32-accurate): per node i,
//   D[l, n] = sum_j nodes[nlist[i,j], l] * edges[i,j,n]
//   g[i, l*16+n] = D[l, n]
// Each operand split x = hi + lo (hi = tf32_rn(x), lo exact residual);
// accumulate hi*hi + lo*hi + hi*lo. Dropped lo*lo ~ 2^-22 relative.
// Dynamic smem (57088 B): raw->hi in place, lo single-buffered.
// ---------------------------------------------------------------------------
#define S1_NB_OFF    0          // float nb[2][32][132]   33792 B (raw, then hi)
#define S1_EG_OFF    33792      // float eg[2][512]        4096 B (raw, then hi)
#define S1_NBLO_OFF  37888      // float nb_lo[32][132]   16896 B
#define S1_EGLO_OFF  54784      // float eg_lo[512]        2048 B
#define S1_SNB_OFF   56832      // int   snb[2][32]         256 B
#define S1_SMEM      57088

__global__ __launch_bounds__(128) void gather_mma(const float* __restrict__ nodes,
                                                  const int*   __restrict__ nl32,
                                                  const float* __restrict__ edges) {
    extern __shared__ __align__(16) char s1mem[];
    float (*nb)[KNB][132] = (float (*)[KNB][132])(s1mem + S1_NB_OFF);
    float (*eg)[512]      = (float (*)[512])(s1mem + S1_EG_OFF);
    float (*nb_lo)[132]   = (float (*)[132])(s1mem + S1_NBLO_OFF);
    float *eg_lo          = (float *)(s1mem + S1_EGLO_OFF);
    int   (*snb)[KNB]     = (int (*)[KNB])(s1mem + S1_SNB_OFF);

    const int tid  = threadIdx.x;
    const int w    = tid >> 5;
    const int strd = gridDim.x;
    const bool is64 = (g_nlist_is64 != 0);

    auto ldidx = [&](long long pos) -> int {
        int idx = is64 ? nl32[2 * pos] : nl32[pos];
        return idx < 0 ? 0 : (idx >= NNODES ? NNODES - 1 : idx);
    };
    auto issue_node = [&](int node, int buf) {
        cp16(&eg[buf][tid * 4], edges + (size_t)node * 512 + tid * 4);
#pragma unroll
        for (int u = 0; u < 8; u++) {
            int q = tid + u * 128;
            int row = q >> 5, seg = q & 31;
            cp16(&nb[buf][row][seg * 4],
                 nodes + (size_t)snb[buf][row] * FDIM + seg * 4);
        }
    };

    int i0 = blockIdx.x;
    if (tid < KNB) snb[0][tid] = ldidx((long long)i0 * KNB + tid);
    __syncthreads();
    issue_node(i0, 0);
    cp_commit();
    if (i0 + strd < NNODES && tid < KNB)
        snb[1][tid] = ldidx((long long)(i0 + strd) * KNB + tid);

    for (int it = 0;; it++) {
        int i = i0 + it * strd;
        if (i >= NNODES) break;
        int b = it & 1;
        int inext = i + strd;

        __syncthreads();   // prev compute (incl. lo arrays) done; snb[b^1] visible
        if (inext < NNODES) issue_node(inext, b ^ 1);
        cp_commit();
        int i2 = i + 2 * strd;
        if (i2 < NNODES && tid < KNB)
            snb[b][tid] = ldidx((long long)i2 * KNB + tid);

        cp_wait<1>();      // node i's group done (next node's may be in flight)
        __syncthreads();

        // Split pass: raw -> (hi in place, lo in single-buffered arrays)
#pragma unroll
        for (int u = 0; u < 8; u++) {
            int q = tid + u * 128;          // float4 index over 32x128 region
            int row = q >> 5, seg = (q & 31) * 4;
            float4* p = (float4*)&nb[b][row][seg];
            float4 v = *p;
            float4 h = make_float4(wmma::__float_to_tf32(v.x), wmma::__float_to_tf32(v.y),
                                   wmma::__float_to_tf32(v.z), wmma::__float_to_tf32(v.w));
            *p = h;
            *(float4*)&nb_lo[row][seg] = make_float4(v.x - h.x, v.y - h.y,
                                                     v.z - h.z, v.w - h.w);
        }
        {
            float4* p = (float4*)&eg[b][tid * 4];
            float4 v = *p;
            float4 h = make_float4(wmma::__float_to_tf32(v.x), wmma::__float_to_tf32(v.y),
                                   wmma::__float_to_tf32(v.z), wmma::__float_to_tf32(v.w));
            *p = h;
            *(float4*)&eg_lo[tid * 4] = make_float4(v.x - h.x, v.y - h.y,
                                                    v.z - h.z, v.w - h.w);
        }
        __syncthreads();

        // Warp w: D[w*32 .. w*32+32, 0..16), K=32 in 4 steps of 8
        wmma::fragment<wmma::accumulator, 16, 16, 8, float> cf[2];
        wmma::fill_fragment(cf[0], 0.0f);
        wmma::fill_fragment(cf[1], 0.0f);
#pragma unroll
        for (int ks = 0; ks < 4; ks++) {
            wmma::fragment<wmma::matrix_b, 16, 16, 8, wmma::precision::tf32, wmma::row_major> bh, bl;
            wmma::load_matrix_sync(bh, &eg[b][ks * 128], 16);
            wmma::load_matrix_sync(bl, &eg_lo[ks * 128], 16);
#pragma unroll
            for (int mi = 0; mi < 2; mi++) {
                wmma::fragment<wmma::matrix_a, 16, 16, 8, wmma::precision::tf32, wmma::col_major> ah, al;
                wmma::load_matrix_sync(ah, &nb[b][ks * 8][w * 32 + mi * 16], 132);
                wmma::load_matrix_sync(al, &nb_lo[ks * 8][w * 32 + mi * 16], 132);
                wmma::mma_sync(cf[mi], ah, bh, cf[mi]);
                wmma::mma_sync(cf[mi], al, bh, cf[mi]);
                wmma::mma_sync(cf[mi], ah, bl, cf[mi]);
            }
        }

        // round to tf32 in regs, store straight to g (row-major, ldm 16 = 64B)
        float* grow = g_buf + (size_t)i * KK;
#pragma unroll
        for (int mi = 0; mi < 2; mi++) {
#pragma unroll
            for (int t = 0; t < cf[mi].num_elements; t++)
                cf[mi].x[t] = wmma::__float_to_tf32(cf[mi].x[t]);
            wmma::store_matrix_sync(grow + (w * 32 + mi * 16) * EDIM,
                                    cf[mi], EDIM, wmma::mem_row_major);
        }
    }
}

// ---------------------------------------------------------------------------
// Stage 2: C = (1/32) * g_buf @ W2   (M=50048, N=128, K=2048), tf32 wmma
// 2-in-flight cp.async pipeline: at iter kb, issue G(kb+1), wait G(kb).
// Epilogue direct to out; last block -> Ctail.
// ---------------------------------------------------------------------------
#define BK 16

__global__ __launch_bounds__(256, 2) void gemm_tf32(float* __restrict__ out) {
    __shared__ __align__(16) float As[2][128][20];   // 80B rows
    __shared__ __align__(16) float Bs[2][BK][132];   // 528B rows

    const int tid = threadIdx.x;
    const int wid = tid >> 5;
    const int warp_m = wid >> 1;   // 0..3
    const int warp_n = wid & 1;    // 0..1
    const size_t row0 = (size_t)blockIdx.x * 128;

    wmma::fragment<wmma::accumulator, 16, 16, 8, float> c[2][4];
#pragma unroll
    for (int mi = 0; mi < 2; mi++)
#pragma unroll
        for (int ni = 0; ni < 4; ni++) wmma::fill_fragment(c[mi][ni], 0.0f);

    auto load_tiles = [&](int buf, int kb) {
        const float* Ab = g_buf + row0 * KK + (size_t)kb * BK;
        const float* Bb = W2 + (size_t)kb * BK * FDIM;
#pragma unroll
        for (int u = 0; u < 2; u++) {
            int q = tid + u * 256;
            int ar = q >> 2, ac = q & 3;
            cp16(&As[buf][ar][ac * 4], Ab + (size_t)ar * KK + ac * 4);
            int br = q >> 5, bc = q & 31;
            cp16(&Bs[buf][br][bc * 4], Bb + br * FDIM + bc * 4);
        }
        cp_commit();
    };

    load_tiles(0, 0);   // G(0)

    const int nkb = KK / BK;  // 128
    for (int kb = 0; kb < nkb; kb++) {
        int cur = kb & 1;

        __syncthreads();                         // buf 'cur' free of prior readers
        if (kb + 1 < nkb) {
            load_tiles(cur ^ 1, kb + 1);         // issue G(kb+1)
            cp_wait<1>();                        // G(kb) complete
        } else {
            cp_wait<0>();
        }
        __syncthreads();                         // tile visible to all warps

#pragma unroll
        for (int kk = 0; kk < 2; kk++) {
            wmma::fragment<wmma::matrix_a, 16, 16, 8, wmma::precision::tf32, wmma::row_major> a[2];
            wmma::fragment<wmma::matrix_b, 16, 16, 8, wmma::precision::tf32, wmma::row_major> b[4];
#pragma unroll
            for (int mi = 0; mi < 2; mi++)
                wmma::load_matrix_sync(a[mi], &As[cur][warp_m * 32 + mi * 16][kk * 8], 20);
#pragma unroll
            for (int ni = 0; ni < 4; ni++)
                wmma::load_matrix_sync(b[ni], &Bs[cur][kk * 8][warp_n * 64 + ni * 16], 132);
#pragma unroll
            for (int mi = 0; mi < 2; mi++)
#pragma unroll
                for (int ni = 0; ni < 4; ni++)
                    wmma::mma_sync(c[mi][ni], a[mi], b[ni], c[mi][ni]);
        }
    }

    const float scale = 1.0f / (float)KNB;
    const bool  last  = (blockIdx.x == (MPAD / 128) - 1);   // rows 49920..50047
#pragma unroll
    for (int mi = 0; mi < 2; mi++)
#pragma unroll
        for (int ni = 0; ni < 4; ni++) {
#pragma unroll
            for (int t = 0; t < c[mi][ni].num_elements; t++) c[mi][ni].x[t] *= scale;
            int rloc = warp_m * 32 + mi * 16;
            int cloc = warp_n * 64 + ni * 16;
            if (!last) {
                wmma::store_matrix_sync(out + (row0 + rloc) * FDIM + cloc,
                                        c[mi][ni], FDIM, wmma::mem_row_major);
            } else {
                wmma::store_matrix_sync(Ctail + rloc * FDIM + cloc,
                                        c[mi][ni], FDIM, wmma::mem_row_major);
            }
        }
}

// last 80 valid rows (49920..49999)
__global__ void copy_tail(float* __restrict__ out) {
    int i = blockIdx.x * 256 + threadIdx.x;
    if (i < 80 * FDIM) out[(size_t)(NNODES - 80) * FDIM + i] = Ctail[i];
}

// ---------------------------------------------------------------------------
extern "C" void kernel_launch(void* const* d_in, const int* in_sizes, int n_in,
                              void* d_out, int out_size) {
    const float* nodes = nullptr;
    const int*   nlist = nullptr;
    const float* edges = nullptr;
    const float* w     = nullptr;
    for (int t = 0; t < n_in; t++) {
        long long s = in_sizes[t];
        if      (s == (long long)NNODES * FDIM)        nodes = (const float*)d_in[t];
        else if (s == (long long)NNODES * KNB)         nlist = (const int*)d_in[t];
        else if (s == (long long)NNODES * KNB * EDIM)  edges = (const float*)d_in[t];
        else if (s == (long long)FDIM * FDIM * EDIM)   w     = (const float*)d_in[t];
    }
    if (!nodes) nodes = (const float*)d_in[0];
    if (!nlist) nlist = (const int*)d_in[1];
    if (!edges) edges = (const float*)d_in[2];
    if (!w)     w     = (const float*)d_in[3];

    float* out = (float*)d_out;

    static bool attr_done = false;
    if (!attr_done) {
        cudaFuncSetAttribute(gather_mma,
                             cudaFuncAttributeMaxDynamicSharedMemorySize, S1_SMEM);
        attr_done = true;
    }

    detect_nlist<<<1, 1>>>(nlist);
    build_w2<<<(KK * FDIM + 255) / 256, 256>>>(w);
    gather_mma<<<GRID1, 128, S1_SMEM>>>(nodes, nlist, edges);
    gemm_tf32<<<MPAD / 128, 256>>>(out);
    copy_tail<<<(80 * FDIM + 255) / 256, 256>>>(out);
}

// round 7
// speedup vs baseline: 1.0484x; 1.0350x over previous
#include <cuda_runtime.h>
#include <mma.h>
#include <cstdint>

using namespace nvcuda;

#define NNODES 50000
#define MPAD   50048
#define FDIM   128
#define KNB    32
#define EDIM   16
#define KK     2048          // FDIM * EDIM
#define GRID1  592           // stage-1 CTAs

__device__ float g_buf[(size_t)MPAD * KK];   // [i][l*16+n], pad rows stay 0
__device__ float W2[KK * FDIM];              // [k=(l*16+n)][m]
__device__ int   g_nlist_is64;

// ---------------------------------------------------------------------------
__global__ void detect_nlist(const int* __restrict__ nl) {
    int odd_or = 0;
#pragma unroll
    for (int t = 1; t < 64; t += 2) odd_or |= nl[t];
    g_nlist_is64 = (odd_or == 0) ? 1 : 0;
}

// W2[(l*16+n)*128 + m] = tf32(w[l,m,n])
__global__ void build_w2(const float* __restrict__ w) {
    int idx = blockIdx.x * 256 + threadIdx.x;
    if (idx < KK * FDIM) {
        int m = idx & (FDIM - 1);
        int k = idx >> 7;
        int l = k >> 4;
        int n = k & (EDIM - 1);
        W2[idx] = wmma::__float_to_tf32(w[(size_t)l * FDIM * EDIM + (size_t)m * EDIM + n]);
    }
}

// ---------------------------------------------------------------------------
__device__ __forceinline__ void cp16(void* s, const void* g) {
    uint32_t sa = (uint32_t)__cvta_generic_to_shared(s);
    asm volatile("cp.async.cg.shared.global [%0], [%1], 16;\n" :: "r"(sa), "l"(g));
}
__device__ __forceinline__ void cp_commit() { asm volatile("cp.async.commit_group;\n"); }
template <int N>
__device__ __forceinline__ void cp_wait() { asm volatile("cp.async.wait_group %0;\n" :: "n"(N)); }

// ---------------------------------------------------------------------------
// Stage 1 (3x tf32 split MMA, fp32-accurate): per node i,
//   D[l, n] = sum_j nodes[nlist[i,j], l] * edges[i,j,n];  g[i, l*16+n] = D[l, n]
// (unchanged from R6 — passing at rel_err 2.9e-4)
// ---------------------------------------------------------------------------
#define S1_NB_OFF    0          // float nb[2][32][132]   33792 B (raw, then hi)
#define S1_EG_OFF    33792      // float eg[2][512]        4096 B (raw, then hi)
#define S1_NBLO_OFF  37888      // float nb_lo[32][132]   16896 B
#define S1_EGLO_OFF  54784      // float eg_lo[512]        2048 B
#define S1_SNB_OFF   56832      // int   snb[2][32]         256 B
#define S1_SMEM      57088

__global__ __launch_bounds__(128) void gather_mma(const float* __restrict__ nodes,
                                                  const int*   __restrict__ nl32,
                                                  const float* __restrict__ edges) {
    extern __shared__ __align__(16) char s1mem[];
    float (*nb)[KNB][132] = (float (*)[KNB][132])(s1mem + S1_NB_OFF);
    float (*eg)[512]      = (float (*)[512])(s1mem + S1_EG_OFF);
    float (*nb_lo)[132]   = (float (*)[132])(s1mem + S1_NBLO_OFF);
    float *eg_lo          = (float *)(s1mem + S1_EGLO_OFF);
    int   (*snb)[KNB]     = (int (*)[KNB])(s1mem + S1_SNB_OFF);

    const int tid  = threadIdx.x;
    const int w    = tid >> 5;
    const int strd = gridDim.x;
    const bool is64 = (g_nlist_is64 != 0);

    auto ldidx = [&](long long pos) -> int {
        int idx = is64 ? nl32[2 * pos] : nl32[pos];
        return idx < 0 ? 0 : (idx >= NNODES ? NNODES - 1 : idx);
    };
    auto issue_node = [&](int node, int buf) {
        cp16(&eg[buf][tid * 4], edges + (size_t)node * 512 + tid * 4);
#pragma unroll
        for (int u = 0; u < 8; u++) {
            int q = tid + u * 128;
            int row = q >> 5, seg = q & 31;
            cp16(&nb[buf][row][seg * 4],
                 nodes + (size_t)snb[buf][row] * FDIM + seg * 4);
        }
    };

    int i0 = blockIdx.x;
    if (tid < KNB) snb[0][tid] = ldidx((long long)i0 * KNB + tid);
    __syncthreads();
    issue_node(i0, 0);
    cp_commit();
    if (i0 + strd < NNODES && tid < KNB)
        snb[1][tid] = ldidx((long long)(i0 + strd) * KNB + tid);

    for (int it = 0;; it++) {
        int i = i0 + it * strd;
        if (i >= NNODES) break;
        int b = it & 1;
        int inext = i + strd;

        __syncthreads();
        if (inext < NNODES) issue_node(inext, b ^ 1);
        cp_commit();
        int i2 = i + 2 * strd;
        if (i2 < NNODES && tid < KNB)
            snb[b][tid] = ldidx((long long)i2 * KNB + tid);

        cp_wait<1>();
        __syncthreads();

        // Split: raw -> (hi in place, lo in single-buffered arrays)
#pragma unroll
        for (int u = 0; u < 8; u++) {
            int q = tid + u * 128;
            int row = q >> 5, seg = (q & 31) * 4;
            float4* p = (float4*)&nb[b][row][seg];
            float4 v = *p;
            float4 h = make_float4(wmma::__float_to_tf32(v.x), wmma::__float_to_tf32(v.y),
                                   wmma::__float_to_tf32(v.z), wmma::__float_to_tf32(v.w));
            *p = h;
            *(float4*)&nb_lo[row][seg] = make_float4(v.x - h.x, v.y - h.y,
                                                     v.z - h.z, v.w - h.w);
        }
        {
            float4* p = (float4*)&eg[b][tid * 4];
            float4 v = *p;
            float4 h = make_float4(wmma::__float_to_tf32(v.x), wmma::__float_to_tf32(v.y),
                                   wmma::__float_to_tf32(v.z), wmma::__float_to_tf32(v.w));
            *p = h;
            *(float4*)&eg_lo[tid * 4] = make_float4(v.x - h.x, v.y - h.y,
                                                    v.z - h.z, v.w - h.w);
        }
        __syncthreads();

        wmma::fragment<wmma::accumulator, 16, 16, 8, float> cf[2];
        wmma::fill_fragment(cf[0], 0.0f);
        wmma::fill_fragment(cf[1], 0.0f);
#pragma unroll
        for (int ks = 0; ks < 4; ks++) {
            wmma::fragment<wmma::matrix_b, 16, 16, 8, wmma::precision::tf32, wmma::row_major> bh, bl;
            wmma::load_matrix_sync(bh, &eg[b][ks * 128], 16);
            wmma::load_matrix_sync(bl, &eg_lo[ks * 128], 16);
#pragma unroll
            for (int mi = 0; mi < 2; mi++) {
                wmma::fragment<wmma::matrix_a, 16, 16, 8, wmma::precision::tf32, wmma::col_major> ah, al;
                wmma::load_matrix_sync(ah, &nb[b][ks * 8][w * 32 + mi * 16], 132);
                wmma::load_matrix_sync(al, &nb_lo[ks * 8][w * 32 + mi * 16], 132);
                wmma::mma_sync(cf[mi], ah, bh, cf[mi]);
                wmma::mma_sync(cf[mi], al, bh, cf[mi]);
                wmma::mma_sync(cf[mi], ah, bl, cf[mi]);
            }
        }

        float* grow = g_buf + (size_t)i * KK;
#pragma unroll
        for (int mi = 0; mi < 2; mi++) {
#pragma unroll
            for (int t = 0; t < cf[mi].num_elements; t++)
                cf[mi].x[t] = wmma::__float_to_tf32(cf[mi].x[t]);
            wmma::store_matrix_sync(grow + (w * 32 + mi * 16) * EDIM,
                                    cf[mi], EDIM, wmma::mem_row_major);
        }
    }
}

// ---------------------------------------------------------------------------
// Stage 2: C = (1/32) * g_buf @ W2   (M=50048, N=128, K=2048), tf32 wmma
// BM=128, BN=128, BK=32, 3-stage cp.async ring, ONE sync per iteration.
// Epilogue: fragment-predicated stores straight to out (no tail kernel;
// 50000-49920=80 is a multiple of 16, so validity is per-fragment clean).
// ---------------------------------------------------------------------------
#define BK2        32
#define STAGES     3
#define AS_STRIDE  36                          // 144B rows
#define AS_BYTES   (128 * AS_STRIDE * 4)       // 18432
#define BS_STRIDE  132                         // 528B rows
#define BS_BYTES   (BK2 * BS_STRIDE * 4)       // 16896
#define STAGE_BYTES (AS_BYTES + BS_BYTES)      // 35328
#define S2_SMEM    (STAGES * STAGE_BYTES)      // 105984

__global__ __launch_bounds__(256, 2) void gemm_tf32(float* __restrict__ out) {
    extern __shared__ __align__(16) char s2mem[];

    const int tid = threadIdx.x;
    const int wid = tid >> 5;
    const int warp_m = wid >> 1;   // 0..3
    const int warp_n = wid & 1;    // 0..1
    const size_t row0 = (size_t)blockIdx.x * 128;

    auto Asm = [&](int s) -> float* { return (float*)(s2mem + s * STAGE_BYTES); };
    auto Bsm = [&](int s) -> float* { return (float*)(s2mem + s * STAGE_BYTES + AS_BYTES); };

    wmma::fragment<wmma::accumulator, 16, 16, 8, float> c[2][4];
#pragma unroll
    for (int mi = 0; mi < 2; mi++)
#pragma unroll
        for (int ni = 0; ni < 4; ni++) wmma::fill_fragment(c[mi][ni], 0.0f);

    auto load_tiles = [&](int s, int kb) {
        const float* Ab = g_buf + row0 * KK + (size_t)kb * BK2;
        const float* Bb = W2 + (size_t)kb * BK2 * FDIM;
        float* A = Asm(s);
        float* B = Bsm(s);
#pragma unroll
        for (int u = 0; u < 4; u++) {          // A: 128 x 32 -> 1024 float4
            int q = tid + u * 256;
            int ar = q >> 3, ac = q & 7;
            cp16(A + ar * AS_STRIDE + ac * 4, Ab + (size_t)ar * KK + ac * 4);
        }
#pragma unroll
        for (int u = 0; u < 4; u++) {          // B: 32 x 128 -> 1024 float4
            int q = tid + u * 256;
            int br = q >> 5, bc = q & 31;
            cp16(B + br * BS_STRIDE + bc * 4, Bb + br * FDIM + bc * 4);
        }
        cp_commit();
    };

    load_tiles(0, 0);
    load_tiles(1, 1);

    const int nkb = KK / BK2;  // 64
    for (int kb = 0; kb < nkb; kb++) {
        int cur = kb % STAGES;

        if (kb + 1 < nkb) cp_wait<1>();   // group kb complete (kb+1 may pend)
        else              cp_wait<0>();
        __syncthreads();                  // all warps past compute(kb-1); tile visible

        if (kb + 2 < nkb) load_tiles((kb + 2) % STAGES, kb + 2);

        const float* A = Asm(cur);
        const float* B = Bsm(cur);
#pragma unroll
        for (int kk = 0; kk < 4; kk++) {
            wmma::fragment<wmma::matrix_a, 16, 16, 8, wmma::precision::tf32, wmma::row_major> a[2];
            wmma::fragment<wmma::matrix_b, 16, 16, 8, wmma::precision::tf32, wmma::row_major> b[4];
#pragma unroll
            for (int mi = 0; mi < 2; mi++)
                wmma::load_matrix_sync(a[mi],
                    A + (warp_m * 32 + mi * 16) * AS_STRIDE + kk * 8, AS_STRIDE);
#pragma unroll
            for (int ni = 0; ni < 4; ni++)
                wmma::load_matrix_sync(b[ni],
                    B + (kk * 8) * BS_STRIDE + warp_n * 64 + ni * 16, BS_STRIDE);
#pragma unroll
            for (int mi = 0; mi < 2; mi++)
#pragma unroll
                for (int ni = 0; ni < 4; ni++)
                    wmma::mma_sync(c[mi][ni], a[mi], b[ni], c[mi][ni]);
        }
    }

    const float scale = 1.0f / (float)KNB;
#pragma unroll
    for (int mi = 0; mi < 2; mi++)
#pragma unroll
        for (int ni = 0; ni < 4; ni++) {
#pragma unroll
            for (int t = 0; t < c[mi][ni].num_elements; t++) c[mi][ni].x[t] *= scale;
            size_t rglob = row0 + warp_m * 32 + mi * 16;
            if (rglob < NNODES)   // 16-row fragment fully valid (80 % 16 == 0)
                wmma::store_matrix_sync(out + rglob * FDIM + warp_n * 64 + ni * 16,
                                        c[mi][ni], FDIM, wmma::mem_row_major);
        }
}

// ---------------------------------------------------------------------------
extern "C" void kernel_launch(void* const* d_in, const int* in_sizes, int n_in,
                              void* d_out, int out_size) {
    const float* nodes = nullptr;
    const int*   nlist = nullptr;
    const float* edges = nullptr;
    const float* w     = nullptr;
    for (int t = 0; t < n_in; t++) {
        long long s = in_sizes[t];
        if      (s == (long long)NNODES * FDIM)        nodes = (const float*)d_in[t];
        else if (s == (long long)NNODES * KNB)         nlist = (const int*)d_in[t];
        else if (s == (long long)NNODES * KNB * EDIM)  edges = (const float*)d_in[t];
        else if (s == (long long)FDIM * FDIM * EDIM)   w     = (const float*)d_in[t];
    }
    if (!nodes) nodes = (const float*)d_in[0];
    if (!nlist) nlist = (const int*)d_in[1];
    if (!edges) edges = (const float*)d_in[2];
    if (!w)     w     = (const float*)d_in[3];

    float* out = (float*)d_out;

    static bool attr_done = false;
    if (!attr_done) {
        cudaFuncSetAttribute(gather_mma,
                             cudaFuncAttributeMaxDynamicSharedMemorySize, S1_SMEM);
        cudaFuncSetAttribute(gemm_tf32,
                             cudaFuncAttributeMaxDynamicSharedMemorySize, S2_SMEM);
        attr_done = true;
    }

    detect_nlist<<<1, 1>>>(nlist);
    build_w2<<<(KK * FDIM + 255) / 256, 256>>>(w);
    gather_mma<<<GRID1, 128, S1_SMEM>>>(nodes, nlist, edges);
    gemm_tf32<<<MPAD / 128, 256, S2_SMEM>>>(out);
}

// round 10
// speedup vs baseline: 1.1690x; 1.1150x over previous
#include <cuda_runtime.h>
#include <mma.h>
#include <cstdint>

using namespace nvcuda;

#define NNODES 50000
#define MPAD   50048
#define FDIM   128
#define KNB    32
#define EDIM   16
#define KK     2048          // FDIM * EDIM
#define KSPLIT 2
#define KHALF  (KK / KSPLIT) // 1024

__device__ float g_buf[(size_t)MPAD * KK];            // [i][l*16+n], pad rows stay 0
__device__ float W2[KK * FDIM];                       // [k=(l*16+n)][m]
__device__ float Cpart[KSPLIT][(size_t)MPAD * FDIM];  // split-K partials
__device__ int   g_nlist_is64;

// ---------------------------------------------------------------------------
__global__ void detect_nlist(const int* __restrict__ nl) {
    int odd_or = 0;
#pragma unroll
    for (int t = 1; t < 64; t += 2) odd_or |= nl[t];
    g_nlist_is64 = (odd_or == 0) ? 1 : 0;
}

// W2[(l*16+n)*128 + m] = tf32(w[l,m,n])
__global__ void build_w2(const float* __restrict__ w) {
    int idx = blockIdx.x * 256 + threadIdx.x;
    if (idx < KK * FDIM) {
        int m = idx & (FDIM - 1);
        int k = idx >> 7;
        int l = k >> 4;
        int n = k & (EDIM - 1);
        W2[idx] = wmma::__float_to_tf32(w[(size_t)l * FDIM * EDIM + (size_t)m * EDIM + n]);
    }
}

// ---------------------------------------------------------------------------
__device__ __forceinline__ void cp16(void* s, const void* g) {
    uint32_t sa = (uint32_t)__cvta_generic_to_shared(s);
    asm volatile("cp.async.cg.shared.global [%0], [%1], 16;\n" :: "r"(sa), "l"(g));
}
__device__ __forceinline__ void cp_commit() { asm volatile("cp.async.commit_group;\n"); }
template <int N>
__device__ __forceinline__ void cp_wait() { asm volatile("cp.async.wait_group %0;\n" :: "n"(N)); }

// ---------------------------------------------------------------------------
// Stage 1 (scalar fp32, exact — R2 version, measured ~250us):
//   g[i, l*16+n] = tf32_round( sum_j nodes[nlist[i,j], l] * edges[i,j,n] )
// One CTA per node, 128 threads (thread = l). nodes (25.6MB) L2-resident.
// ---------------------------------------------------------------------------
__global__ void gather_contract(const float* __restrict__ nodes,
                                const int* __restrict__ nlist32,
                                const float* __restrict__ edges) {
    int i = blockIdx.x;
    int l = threadIdx.x;  // 0..127

    __shared__ __align__(16) float se[KNB * EDIM];  // 512 floats
    __shared__ int snb[KNB];

    ((float4*)se)[l] = ((const float4*)(edges + (size_t)i * KNB * EDIM))[l];
    if (l < KNB) {
        int pos = i * KNB + l;
        int idx = g_nlist_is64 ? nlist32[2 * (size_t)pos] : nlist32[pos];
        idx = idx < 0 ? 0 : (idx >= NNODES ? NNODES - 1 : idx);
        snb[l] = idx;
    }
    __syncthreads();

    float acc[EDIM];
#pragma unroll
    for (int n = 0; n < EDIM; n++) acc[n] = 0.f;

#pragma unroll 4
    for (int j = 0; j < KNB; j++) {
        float v = __ldg(nodes + (size_t)snb[j] * FDIM + l);
#pragma unroll
        for (int n = 0; n < EDIM; n++)
            acc[n] = fmaf(v, se[j * EDIM + n], acc[n]);
    }

    float4* g4 = (float4*)(g_buf + (size_t)i * KK + (size_t)l * EDIM);
#pragma unroll
    for (int q = 0; q < 4; q++) {
        g4[q] = make_float4(wmma::__float_to_tf32(acc[q * 4 + 0]),
                            wmma::__float_to_tf32(acc[q * 4 + 1]),
                            wmma::__float_to_tf32(acc[q * 4 + 2]),
                            wmma::__float_to_tf32(acc[q * 4 + 3]));
    }
}

// ---------------------------------------------------------------------------
// Stage 2: split-K tf32 wmma GEMM.
// Cpart[kh] = g[:, kh*1024 : (kh+1)*1024] @ W2[kh*1024 : ..., :]
// BM=128, BN=128, BK=32, 3-stage cp.async ring, 1 sync/iter, 32 iters.
// grid = (391, 2); blockIdx.y = K-half.
// ---------------------------------------------------------------------------
#define BK2        32
#define STAGES     3
#define AS_STRIDE  36
#define AS_BYTES   (128 * AS_STRIDE * 4)       // 18432
#define BS_STRIDE  132
#define BS_BYTES   (BK2 * BS_STRIDE * 4)       // 16896
#define STAGE_BYTES (AS_BYTES + BS_BYTES)      // 35328
#define S2_SMEM    (STAGES * STAGE_BYTES)      // 105984

__global__ __launch_bounds__(256, 2) void gemm_tf32() {
    extern __shared__ __align__(16) char s2mem[];

    const int tid = threadIdx.x;
    const int wid = tid >> 5;
    const int warp_m = wid >> 1;   // 0..3
    const int warp_n = wid & 1;    // 0..1
    const size_t row0 = (size_t)blockIdx.x * 128;
    const int    koff = blockIdx.y * KHALF;
    float* Cp = &Cpart[blockIdx.y][0];

    auto Asm = [&](int s) -> float* { return (float*)(s2mem + s * STAGE_BYTES); };
    auto Bsm = [&](int s) -> float* { return (float*)(s2mem + s * STAGE_BYTES + AS_BYTES); };

    wmma::fragment<wmma::accumulator, 16, 16, 8, float> c[2][4];
#pragma unroll
    for (int mi = 0; mi < 2; mi++)
#pragma unroll
        for (int ni = 0; ni < 4; ni++) wmma::fill_fragment(c[mi][ni], 0.0f);

    auto load_tiles = [&](int s, int kb) {
        const float* Ab = g_buf + row0 * KK + (size_t)(koff + kb * BK2);
        const float* Bb = W2 + (size_t)(koff + kb * BK2) * FDIM;
        float* A = Asm(s);
        float* B = Bsm(s);
#pragma unroll
        for (int u = 0; u < 4; u++) {          // A: 128 x 32 -> 1024 float4
            int q = tid + u * 256;
            int ar = q >> 3, ac = q & 7;
            cp16(A + ar * AS_STRIDE + ac * 4, Ab + (size_t)ar * KK + ac * 4);
        }
#pragma unroll
        for (int u = 0; u < 4; u++) {          // B: 32 x 128 -> 1024 float4
            int q = tid + u * 256;
            int br = q >> 5, bc = q & 31;
            cp16(B + br * BS_STRIDE + bc * 4, Bb + br * FDIM + bc * 4);
        }
        cp_commit();
    };

    load_tiles(0, 0);
    load_tiles(1, 1);

    const int nkb = KHALF / BK2;  // 32
    for (int kb = 0; kb < nkb; kb++) {
        int cur = kb % STAGES;

        if (kb + 1 < nkb) cp_wait<1>();
        else              cp_wait<0>();
        __syncthreads();

        if (kb + 2 < nkb) load_tiles((kb + 2) % STAGES, kb + 2);

        const float* A = Asm(cur);
        const float* B = Bsm(cur);
#pragma unroll
        for (int kk = 0; kk < 4; kk++) {
            wmma::fragment<wmma::matrix_a, 16, 16, 8, wmma::precision::tf32, wmma::row_major> a[2];
            wmma::fragment<wmma::matrix_b, 16, 16, 8, wmma::precision::tf32, wmma::row_major> b[4];
#pragma unroll
            for (int mi = 0; mi < 2; mi++)
                wmma::load_matrix_sync(a[mi],
                    A + (warp_m * 32 + mi * 16) * AS_STRIDE + kk * 8, AS_STRIDE);
#pragma unroll
            for (int ni = 0; ni < 4; ni++)
                wmma::load_matrix_sync(b[ni],
                    B + (kk * 8) * BS_STRIDE + warp_n * 64 + ni * 16, BS_STRIDE);
#pragma unroll
            for (int mi = 0; mi < 2; mi++)
#pragma unroll
                for (int ni = 0; ni < 4; ni++)
                    wmma::mma_sync(c[mi][ni], a[mi], b[ni], c[mi][ni]);
        }
    }

#pragma unroll
    for (int mi = 0; mi < 2; mi++)
#pragma unroll
        for (int ni = 0; ni < 4; ni++) {
            size_t rglob = row0 + warp_m * 32 + mi * 16;
            if (rglob < NNODES)   // 16-row fragments fully valid (80 % 16 == 0)
                wmma::store_matrix_sync(Cp + rglob * FDIM + warp_n * 64 + ni * 16,
                                        c[mi][ni], FDIM, wmma::mem_row_major);
        }
}

// ---------------------------------------------------------------------------
// Reduce: out = (Cpart0 + Cpart1) / 32   (valid rows only), float4.
// ---------------------------------------------------------------------------
__global__ void reduce_out(float* __restrict__ out) {
    size_t i = (size_t)blockIdx.x * 256 + threadIdx.x;
    if (i < (size_t)NNODES * FDIM / 4) {
        float4 a = ((const float4*)&Cpart[0][0])[i];
        float4 b = ((const float4*)&Cpart[1][0])[i];
        const float s = 1.0f / (float)KNB;
        ((float4*)out)[i] = make_float4((a.x + b.x) * s, (a.y + b.y) * s,
                                        (a.z + b.z) * s, (a.w + b.w) * s);
    }
}

// ---------------------------------------------------------------------------
extern "C" void kernel_launch(void* const* d_in, const int* in_sizes, int n_in,
                              void* d_out, int out_size) {
    const float* nodes = nullptr;
    const int*   nlist = nullptr;
    const float* edges = nullptr;
    const float* w     = nullptr;
    for (int t = 0; t < n_in; t++) {
        long long s = in_sizes[t];
        if      (s == (long long)NNODES * FDIM)        nodes = (const float*)d_in[t];
        else if (s == (long long)NNODES * KNB)         nlist = (const int*)d_in[t];
        else if (s == (long long)NNODES * KNB * EDIM)  edges = (const float*)d_in[t];
        else if (s == (long long)FDIM * FDIM * EDIM)   w     = (const float*)d_in[t];
    }
    if (!nodes) nodes = (const float*)d_in[0];
    if (!nlist) nlist = (const int*)d_in[1];
    if (!edges) edges = (const float*)d_in[2];
    if (!w)     w     = (const float*)d_in[3];

    float* out = (float*)d_out;

    static bool attr_done = false;
    if (!attr_done) {
        cudaFuncSetAttribute(gemm_tf32,
                             cudaFuncAttributeMaxDynamicSharedMemorySize, S2_SMEM);
        attr_done = true;
    }

    detect_nlist<<<1, 1>>>(nlist);
    build_w2<<<(KK * FDIM + 255) / 256, 256>>>(w);
    gather_contract<<<NNODES, FDIM>>>(nodes, nlist, edges);
    gemm_tf32<<<dim3(MPAD / 128, KSPLIT), 256, S2_SMEM>>>();
    reduce_out<<<((NNODES * FDIM / 4) + 255) / 256, 256>>>(out);
}